// round 1
// baseline (speedup 1.0000x reference)
#include <cuda_runtime.h>
#include <cuda_bf16.h>
#include <math.h>

// ---------------- problem constants ----------------
#define BB   4
#define TT   256
#define TAA  1500
#define DD   768
#define HH   12
#define LL   12
#define VV   51865
#define DHH  64
#define BT   (BB*TT)          // 1024
#define SCALE_Q 0.125f

// ---------------- scratch (static device globals; allocation-free) ----------------
__device__ float g_x  [BT*DD];                 // residual stream
__device__ float g_h  [BT*DD];                 // LN output
__device__ float g_q  [BT*DD];                 // q / q2
__device__ float g_o  [BT*DD];                 // attention output (pre out-proj)
__device__ float g_sc [(size_t)BB*HH*TT*TAA];  // scores (self reuses prefix)
__device__ float g_ck [(size_t)BB*TAA*DD];     // cross keys
__device__ float g_cv [(size_t)BB*TAA*DD];     // cross values
__device__ float g_hid[(size_t)BT*4*DD];       // MLP hidden

// ---------------- GEMM: C = act((A@B + bias)*scale) + res ----------------
// Tiles: 64x64x16, 256 threads, 4x4 per thread. Batched via blockIdx.z with
// two-level offsets: off = (z/Hd)*s0 + (z%Hd)*s1 for A, B, C (res uses C's).
#define GBM 64
#define GBN 64
#define GBK 16

__global__ __launch_bounds__(256) void gemm_nn_kernel(
    int M, int N, int K,
    const float* __restrict__ A, int lda, long sA0, long sA1,
    const float* __restrict__ B, int ldb, long sB0, long sB1,
    float* __restrict__ C, int ldc, long sC0, long sC1,
    int Hd, const float* __restrict__ bias, const float* __restrict__ res,
    float scale, int act)
{
    __shared__ float As[GBK][GBM];
    __shared__ float Bs[GBK][GBN];
    int z = blockIdx.z;
    int zb = z / Hd, zh = z % Hd;
    A += zb * sA0 + zh * sA1;
    B += zb * sB0 + zh * sB1;
    C += zb * sC0 + zh * sC1;
    const float* R = res ? (res + zb * sC0 + zh * sC1) : nullptr;

    int tid = threadIdx.x;
    int tx = tid & 15, ty = tid >> 4;
    int bm = blockIdx.y * GBM, bn = blockIdx.x * GBN;

    float acc[4][4];
#pragma unroll
    for (int i = 0; i < 4; i++)
#pragma unroll
        for (int j = 0; j < 4; j++) acc[i][j] = 0.f;

    for (int kk = 0; kk < K; kk += GBK) {
#pragma unroll
        for (int i = 0; i < 4; i++) {
            int idx = i * 256 + tid;
            int r = idx >> 4, c = idx & 15;          // 64 rows x 16 cols
            float v = 0.f;
            if (bm + r < M && kk + c < K) v = A[(long)(bm + r) * lda + kk + c];
            As[c][r] = v;
        }
#pragma unroll
        for (int i = 0; i < 4; i++) {
            int idx = i * 256 + tid;
            int r = idx >> 6, c = idx & 63;          // 16 rows x 64 cols
            float v = 0.f;
            if (kk + r < K && bn + c < N) v = B[(long)(kk + r) * ldb + bn + c];
            Bs[r][c] = v;
        }
        __syncthreads();
#pragma unroll
        for (int k = 0; k < GBK; k++) {
            float a0 = As[k][ty * 4 + 0];
            float a1 = As[k][ty * 4 + 1];
            float a2 = As[k][ty * 4 + 2];
            float a3 = As[k][ty * 4 + 3];
            float4 b = *(const float4*)&Bs[k][tx * 4];
            acc[0][0] += a0 * b.x; acc[0][1] += a0 * b.y; acc[0][2] += a0 * b.z; acc[0][3] += a0 * b.w;
            acc[1][0] += a1 * b.x; acc[1][1] += a1 * b.y; acc[1][2] += a1 * b.z; acc[1][3] += a1 * b.w;
            acc[2][0] += a2 * b.x; acc[2][1] += a2 * b.y; acc[2][2] += a2 * b.z; acc[2][3] += a2 * b.w;
            acc[3][0] += a3 * b.x; acc[3][1] += a3 * b.y; acc[3][2] += a3 * b.z; acc[3][3] += a3 * b.w;
        }
        __syncthreads();
    }

#pragma unroll
    for (int i = 0; i < 4; i++) {
        int row = bm + ty * 4 + i;
        if (row >= M) continue;
#pragma unroll
        for (int j = 0; j < 4; j++) {
            int col = bn + tx * 4 + j;
            if (col >= N) continue;
            float v = acc[i][j];
            if (bias) v += bias[col];
            v *= scale;
            if (act == 1) v = 0.5f * v * (1.f + erff(v * 0.70710678118654752f));
            long ci = (long)row * ldc + col;
            if (R) v += R[ci];
            C[ci] = v;
        }
    }
}

// C = A @ B^T  (B is [N,K] row-major)
__global__ __launch_bounds__(256) void gemm_nt_kernel(
    int M, int N, int K,
    const float* __restrict__ A, int lda, long sA0, long sA1,
    const float* __restrict__ B, int ldb, long sB0, long sB1,
    float* __restrict__ C, int ldc, long sC0, long sC1,
    int Hd, float scale)
{
    __shared__ float As[GBK][GBM];
    __shared__ float Bs[GBK][GBN];
    int z = blockIdx.z;
    int zb = z / Hd, zh = z % Hd;
    A += zb * sA0 + zh * sA1;
    B += zb * sB0 + zh * sB1;
    C += zb * sC0 + zh * sC1;

    int tid = threadIdx.x;
    int tx = tid & 15, ty = tid >> 4;
    int bm = blockIdx.y * GBM, bn = blockIdx.x * GBN;

    float acc[4][4];
#pragma unroll
    for (int i = 0; i < 4; i++)
#pragma unroll
        for (int j = 0; j < 4; j++) acc[i][j] = 0.f;

    for (int kk = 0; kk < K; kk += GBK) {
#pragma unroll
        for (int i = 0; i < 4; i++) {
            int idx = i * 256 + tid;
            int r = idx >> 4, c = idx & 15;
            float v = 0.f;
            if (bm + r < M && kk + c < K) v = A[(long)(bm + r) * lda + kk + c];
            As[c][r] = v;
        }
#pragma unroll
        for (int i = 0; i < 4; i++) {
            int idx = i * 256 + tid;
            int n = idx >> 4, k = idx & 15;          // 64 n-rows x 16 k-cols
            float v = 0.f;
            if (bn + n < N && kk + k < K) v = B[(long)(bn + n) * ldb + kk + k];
            Bs[k][n] = v;
        }
        __syncthreads();
#pragma unroll
        for (int k = 0; k < GBK; k++) {
            float a0 = As[k][ty * 4 + 0];
            float a1 = As[k][ty * 4 + 1];
            float a2 = As[k][ty * 4 + 2];
            float a3 = As[k][ty * 4 + 3];
            float4 b = *(const float4*)&Bs[k][tx * 4];
            acc[0][0] += a0 * b.x; acc[0][1] += a0 * b.y; acc[0][2] += a0 * b.z; acc[0][3] += a0 * b.w;
            acc[1][0] += a1 * b.x; acc[1][1] += a1 * b.y; acc[1][2] += a1 * b.z; acc[1][3] += a1 * b.w;
            acc[2][0] += a2 * b.x; acc[2][1] += a2 * b.y; acc[2][2] += a2 * b.z; acc[2][3] += a2 * b.w;
            acc[3][0] += a3 * b.x; acc[3][1] += a3 * b.y; acc[3][2] += a3 * b.z; acc[3][3] += a3 * b.w;
        }
        __syncthreads();
    }

#pragma unroll
    for (int i = 0; i < 4; i++) {
        int row = bm + ty * 4 + i;
        if (row >= M) continue;
#pragma unroll
        for (int j = 0; j < 4; j++) {
            int col = bn + tx * 4 + j;
            if (col >= N) continue;
            C[(long)row * ldc + col] = acc[i][j] * scale;
        }
    }
}

// ---------------- elementwise / row kernels ----------------
__global__ __launch_bounds__(256) void embed_kernel(
    const int* __restrict__ tokens, const float* __restrict__ tok_emb,
    const float* __restrict__ pos_emb, float* __restrict__ x)
{
    int row = blockIdx.x;            // b*T + t
    int t = row % TT;
    int tok = tokens[row];
    const float* te = tok_emb + (long)tok * DD;
    const float* pe = pos_emb + (long)t * DD;
    float* xr = x + (long)row * DD;
#pragma unroll
    for (int it = 0; it < 3; it++) {
        int j = threadIdx.x + it * 256;
        xr[j] = te[j] + pe[j];
    }
}

__global__ __launch_bounds__(256) void ln_kernel(
    const float* __restrict__ x, float* __restrict__ y,
    const float* __restrict__ g, const float* __restrict__ b)
{
    __shared__ float red[256];
    int row = blockIdx.x;
    const float* xr = x + (long)row * DD;
    float* yr = y + (long)row * DD;
    int tid = threadIdx.x;
    float v0 = xr[tid], v1 = xr[tid + 256], v2 = xr[tid + 512];
    float s = v0 + v1 + v2;
    red[tid] = s; __syncthreads();
    for (int st = 128; st > 0; st >>= 1) { if (tid < st) red[tid] += red[tid + st]; __syncthreads(); }
    float mean = red[0] * (1.f / DD);
    __syncthreads();
    float d0 = v0 - mean, d1 = v1 - mean, d2 = v2 - mean;
    red[tid] = d0 * d0 + d1 * d1 + d2 * d2; __syncthreads();
    for (int st = 128; st > 0; st >>= 1) { if (tid < st) red[tid] += red[tid + st]; __syncthreads(); }
    float inv = rsqrtf(red[0] * (1.f / DD) + 1e-5f);
    yr[tid]       = d0 * inv * g[tid]       + b[tid];
    yr[tid + 256] = d1 * inv * g[tid + 256] + b[tid + 256];
    yr[tid + 512] = d2 * inv * g[tid + 512] + b[tid + 512];
}

// causal softmax: rows of length T=256, row index -> (z, i)
__global__ __launch_bounds__(256) void softmax_causal_kernel(float* __restrict__ S)
{
    __shared__ float red[256];
    int row = blockIdx.x;
    int i = row & (TT - 1);
    float* p = S + (long)row * TT;
    int tid = threadIdx.x;
    float v = (tid <= i) ? p[tid] : -1e30f;
    red[tid] = v; __syncthreads();
    for (int st = 128; st > 0; st >>= 1) { if (tid < st) red[tid] = fmaxf(red[tid], red[tid + st]); __syncthreads(); }
    float m = red[0]; __syncthreads();
    float e = (tid <= i) ? expf(v - m) : 0.f;
    red[tid] = e; __syncthreads();
    for (int st = 128; st > 0; st >>= 1) { if (tid < st) red[tid] += red[tid + st]; __syncthreads(); }
    p[tid] = e / red[0];
}

// plain softmax over rows of length len (<= 1536)
__global__ __launch_bounds__(256) void softmax_plain_kernel(float* __restrict__ S, int len)
{
    __shared__ float red[256];
    int row = blockIdx.x;
    float* p = S + (long)row * len;
    int tid = threadIdx.x;
    float vals[6];
    float m = -1e30f;
#pragma unroll
    for (int it = 0; it < 6; it++) {
        int j = tid + it * 256;
        float v = (j < len) ? p[j] : -1e30f;
        vals[it] = v;
        m = fmaxf(m, v);
    }
    red[tid] = m; __syncthreads();
    for (int st = 128; st > 0; st >>= 1) { if (tid < st) red[tid] = fmaxf(red[tid], red[tid + st]); __syncthreads(); }
    m = red[0]; __syncthreads();
    float s = 0.f;
#pragma unroll
    for (int it = 0; it < 6; it++) {
        int j = tid + it * 256;
        float e = (j < len) ? expf(vals[it] - m) : 0.f;
        vals[it] = e;
        s += e;
    }
    red[tid] = s; __syncthreads();
    for (int st = 128; st > 0; st >>= 1) { if (tid < st) red[tid] += red[tid + st]; __syncthreads(); }
    float inv = 1.f / red[0];
#pragma unroll
    for (int it = 0; it < 6; it++) {
        int j = tid + it * 256;
        if (j < len) p[j] = vals[it] * inv;
    }
}

// ---------------- host-side launch helpers ----------------
static inline void launch_nn(int M, int N, int K,
                             const float* A, int lda, long sA0, long sA1,
                             const float* B, int ldb, long sB0, long sB1,
                             float* C, int ldc, long sC0, long sC1,
                             int batch, int Hd,
                             const float* bias, const float* res,
                             float scale, int act)
{
    dim3 g((N + GBN - 1) / GBN, (M + GBM - 1) / GBM, batch);
    gemm_nn_kernel<<<g, 256>>>(M, N, K, A, lda, sA0, sA1, B, ldb, sB0, sB1,
                               C, ldc, sC0, sC1, Hd, bias, res, scale, act);
}

static inline void launch_nt(int M, int N, int K,
                             const float* A, int lda, long sA0, long sA1,
                             const float* B, int ldb, long sB0, long sB1,
                             float* C, int ldc, long sC0, long sC1,
                             int batch, int Hd, float scale)
{
    dim3 g((N + GBN - 1) / GBN, (M + GBM - 1) / GBM, batch);
    gemm_nt_kernel<<<g, 256>>>(M, N, K, A, lda, sA0, sA1, B, ldb, sB0, sB1,
                               C, ldc, sC0, sC1, Hd, scale);
}

extern "C" void kernel_launch(void* const* d_in, const int* in_sizes, int n_in,
                              void* d_out, int out_size)
{
    (void)in_sizes; (void)n_in; (void)out_size;

    const int*   tokens  = (const int*)  d_in[0];
    const float* xa      = (const float*)d_in[1];
    const float* tok_emb = (const float*)d_in[2];
    const float* pos_emb = (const float*)d_in[3];
    const float* Wq      = (const float*)d_in[4];
    const float* bq      = (const float*)d_in[5];
    const float* Wk      = (const float*)d_in[6];
    const float* Wv      = (const float*)d_in[7];
    const float* bv      = (const float*)d_in[8];
    const float* Wo      = (const float*)d_in[9];
    const float* bo      = (const float*)d_in[10];
    const float* ln1_g   = (const float*)d_in[11];
    const float* ln1_b   = (const float*)d_in[12];
    const float* Wcq     = (const float*)d_in[13];
    const float* bcq     = (const float*)d_in[14];
    const float* Wck     = (const float*)d_in[15];
    const float* Wcv     = (const float*)d_in[16];
    const float* bcv     = (const float*)d_in[17];
    const float* Wco     = (const float*)d_in[18];
    const float* bco     = (const float*)d_in[19];
    const float* ln2_g   = (const float*)d_in[20];
    const float* ln2_b   = (const float*)d_in[21];
    const float* W1      = (const float*)d_in[22];
    const float* b1      = (const float*)d_in[23];
    const float* W2      = (const float*)d_in[24];
    const float* b2      = (const float*)d_in[25];
    const float* ln3_g   = (const float*)d_in[26];
    const float* ln3_b   = (const float*)d_in[27];
    const float* lnf_g   = (const float*)d_in[28];
    const float* lnf_b   = (const float*)d_in[29];

    float* out = (float*)d_out;
    float* out_logits = out;                                    // [B,T,V]
    float* out_chw    = out_logits + (size_t)BB * TT * VV;      // [(L/2)*H,T,TA]
    float* out_kv     = out_chw + (size_t)(LL / 2) * HH * TT * TAA; // [2L,B,T,D]

    float *x, *h, *q, *o, *sc, *ck, *cv, *hid;
    cudaGetSymbolAddress((void**)&x,   g_x);
    cudaGetSymbolAddress((void**)&h,   g_h);
    cudaGetSymbolAddress((void**)&q,   g_q);
    cudaGetSymbolAddress((void**)&o,   g_o);
    cudaGetSymbolAddress((void**)&sc,  g_sc);
    cudaGetSymbolAddress((void**)&ck,  g_ck);
    cudaGetSymbolAddress((void**)&cv,  g_cv);
    cudaGetSymbolAddress((void**)&hid, g_hid);

    // embeddings
    embed_kernel<<<BT, 256>>>(tokens, tok_emb, pos_emb, x);

    const long DTD = (long)TT * DD;        // per-b stride in [B,T,D]
    const long TAD = (long)TAA * DD;       // per-b stride in [B,TA,D]

    for (int l = 0; l < LL; l++) {
        const float* Wq_l = Wq + (size_t)l * DD * DD;
        const float* Wk_l = Wk + (size_t)l * DD * DD;
        const float* Wv_l = Wv + (size_t)l * DD * DD;
        const float* Wo_l = Wo + (size_t)l * DD * DD;
        const float* Wcq_l = Wcq + (size_t)l * DD * DD;
        const float* Wck_l = Wck + (size_t)l * DD * DD;
        const float* Wcv_l = Wcv + (size_t)l * DD * DD;
        const float* Wco_l = Wco + (size_t)l * DD * DD;
        const float* W1_l = W1 + (size_t)l * DD * 4 * DD;
        const float* W2_l = W2 + (size_t)l * 4 * DD * DD;

        float* kout = out_kv + (size_t)(2 * l) * BT * DD;      // [B,T,D]
        float* vout = out_kv + (size_t)(2 * l + 1) * BT * DD;

        // ---- self attention ----
        ln_kernel<<<BT, 256>>>(x, h, ln1_g + l * DD, ln1_b + l * DD);
        launch_nn(BT, DD, DD, h, DD, 0, 0, Wq_l, DD, 0, 0, q, DD, 0, 0, 1, 1,
                  bq + l * DD, nullptr, SCALE_Q, 0);
        launch_nn(BT, DD, DD, h, DD, 0, 0, Wk_l, DD, 0, 0, kout, DD, 0, 0, 1, 1,
                  nullptr, nullptr, 1.f, 0);
        launch_nn(BT, DD, DD, h, DD, 0, 0, Wv_l, DD, 0, 0, vout, DD, 0, 0, 1, 1,
                  bv + l * DD, nullptr, 1.f, 0);
        // scores = q @ k^T  (batched over b,h)
        launch_nt(TT, TT, DHH,
                  q,    DD, DTD, DHH,
                  kout, DD, DTD, DHH,
                  sc,   TT, (long)HH * TT * TT, (long)TT * TT,
                  BB * HH, HH, 1.f);
        softmax_causal_kernel<<<BB * HH * TT, 256>>>(sc);
        // o = P @ v
        launch_nn(TT, DHH, TT,
                  sc,   TT, (long)HH * TT * TT, (long)TT * TT,
                  vout, DD, DTD, DHH,
                  o,    DD, DTD, DHH,
                  BB * HH, HH, nullptr, nullptr, 1.f, 0);
        // x += o @ Wo + bo
        launch_nn(BT, DD, DD, o, DD, 0, 0, Wo_l, DD, 0, 0, x, DD, 0, 0, 1, 1,
                  bo + l * DD, x, 1.f, 0);

        // ---- cross attention ----
        ln_kernel<<<BT, 256>>>(x, h, ln2_g + l * DD, ln2_b + l * DD);
        launch_nn(BT, DD, DD, h, DD, 0, 0, Wcq_l, DD, 0, 0, q, DD, 0, 0, 1, 1,
                  bcq + l * DD, nullptr, SCALE_Q, 0);
        launch_nn(BB * TAA, DD, DD, xa, DD, 0, 0, Wck_l, DD, 0, 0, ck, DD, 0, 0, 1, 1,
                  nullptr, nullptr, 1.f, 0);
        launch_nn(BB * TAA, DD, DD, xa, DD, 0, 0, Wcv_l, DD, 0, 0, cv, DD, 0, 0, 1, 1,
                  bcv + l * DD, nullptr, 1.f, 0);
        // qk2 = q2 @ ck^T  -> [b,h,T,TA]
        launch_nt(TT, TAA, DHH,
                  q,  DD, DTD, DHH,
                  ck, DD, TAD, DHH,
                  sc, TAA, (long)HH * TT * TAA, (long)TT * TAA,
                  BB * HH, HH, 1.f);
        if (l >= LL / 2) {
            // beam 0 pre-softmax scores = first H*T*TA elements, layout [h,t,ta]
            cudaMemcpyAsync(out_chw + (size_t)(l - LL / 2) * HH * TT * TAA, sc,
                            sizeof(float) * (size_t)HH * TT * TAA,
                            cudaMemcpyDeviceToDevice);
        }
        softmax_plain_kernel<<<BB * HH * TT, 256>>>(sc, TAA);
        // o2 = P2 @ cv
        launch_nn(TT, DHH, TAA,
                  sc, TAA, (long)HH * TT * TAA, (long)TT * TAA,
                  cv, DD, TAD, DHH,
                  o,  DD, DTD, DHH,
                  BB * HH, HH, nullptr, nullptr, 1.f, 0);
        // x += o2 @ Wco + bco
        launch_nn(BT, DD, DD, o, DD, 0, 0, Wco_l, DD, 0, 0, x, DD, 0, 0, 1, 1,
                  bco + l * DD, x, 1.f, 0);

        // ---- MLP ----
        ln_kernel<<<BT, 256>>>(x, h, ln3_g + l * DD, ln3_b + l * DD);
        launch_nn(BT, 4 * DD, DD, h, DD, 0, 0, W1_l, 4 * DD, 0, 0, hid, 4 * DD, 0, 0,
                  1, 1, b1 + (size_t)l * 4 * DD, nullptr, 1.f, 1);
        launch_nn(BT, DD, 4 * DD, hid, 4 * DD, 0, 0, W2_l, DD, 0, 0, x, DD, 0, 0,
                  1, 1, b2 + l * DD, x, 1.f, 0);
    }

    // final LN + tied-embedding logits
    ln_kernel<<<BT, 256>>>(x, h, lnf_g, lnf_b);
    launch_nt(BT, VV, DD,
              h, DD, 0, 0,
              tok_emb, DD, 0, 0,
              out_logits, VV, 0, 0,
              1, 1, 1.f);
}

// round 2
// speedup vs baseline: 2.2265x; 2.2265x over previous
#include <cuda_runtime.h>
#include <cuda_bf16.h>
#include <math.h>
#include <stdint.h>

// ---------------- problem constants ----------------
#define BB   4
#define TT   256
#define TAA  1500
#define DD   768
#define HH   12
#define LL   12
#define VV   51865
#define DHH  64
#define BT   (BB*TT)          // 1024
#define SCALE_Q 0.125f

// ---------------- scratch (static device globals; allocation-free) ----------------
__device__ float g_x  [BT*DD];                 // residual stream
__device__ float g_h  [BT*DD];                 // LN output
__device__ float g_q  [BT*DD];                 // q / q2
__device__ float g_o  [BT*DD];                 // attention output (pre out-proj)
__device__ float g_sc [(size_t)BB*HH*TT*TAA];  // scores (self reuses prefix)
__device__ float g_ck [(size_t)BB*TAA*DD];     // cross keys
__device__ float g_cv [(size_t)BB*TAA*DD];     // cross values
__device__ float g_hid[(size_t)BT*4*DD];       // MLP hidden

// ---------------- TF32 tensor-core GEMM ----------------
// C = act((A@B(^T) + bias)*scale) + res
// Block tile 64x64x16, 128 threads (4 warps, 2x2), warp tile 32x32.
// mma.sync.aligned.m16n8k8.row.col.f32.tf32.tf32.f32
// Batched via blockIdx.z with two-level offsets (z/Hd)*s0 + (z%Hd)*s1.
#define TBM 64
#define TBN 64
#define TBK 16
#define AS_LD 20   // 64 x 20 floats: (g*20 + tig) mod 32 all distinct -> conflict-free frag loads
#define BS_LD 72   // 16 x 72 floats: (tig*72 + g) mod 32 = 8*tig+g distinct -> conflict-free

__device__ __forceinline__ float to_tf32(float x) {
    uint32_t u;
    asm("cvt.rna.tf32.f32 %0, %1;" : "=r"(u) : "f"(x));
    return __uint_as_float(u);
}

__device__ __forceinline__ void mma_tf32(float& c0, float& c1, float& c2, float& c3,
                                         uint32_t a0, uint32_t a1, uint32_t a2, uint32_t a3,
                                         uint32_t b0, uint32_t b1) {
    asm volatile(
        "mma.sync.aligned.m16n8k8.row.col.f32.tf32.tf32.f32 "
        "{%0,%1,%2,%3}, {%4,%5,%6,%7}, {%8,%9}, {%0,%1,%2,%3};"
        : "+f"(c0), "+f"(c1), "+f"(c2), "+f"(c3)
        : "r"(a0), "r"(a1), "r"(a2), "r"(a3), "r"(b0), "r"(b1));
}

template <int NT>
__global__ __launch_bounds__(128) void gemm_tf32_kernel(
    int M, int N, int K,
    const float* __restrict__ A, int lda, long sA0, long sA1,
    const float* __restrict__ B, int ldb, long sB0, long sB1,
    float* __restrict__ C, int ldc, long sC0, long sC1,
    int Hd, const float* __restrict__ bias, const float* __restrict__ res,
    float scale, int act)
{
    __shared__ float As[TBM][AS_LD];
    __shared__ float Bs[TBK][BS_LD];

    int z = blockIdx.z;
    int zb = z / Hd, zh = z % Hd;
    A += zb * sA0 + zh * sA1;
    B += zb * sB0 + zh * sB1;
    C += zb * sC0 + zh * sC1;
    const float* R = res ? (res + zb * sC0 + zh * sC1) : nullptr;

    int tid  = threadIdx.x;
    int lane = tid & 31;
    int warp = tid >> 5;
    int g    = lane >> 2;     // groupID 0..7
    int tig  = lane & 3;      // threadID_in_group 0..3
    int warpM = warp & 1, warpN = warp >> 1;
    int m0w = warpM * 32, n0w = warpN * 32;

    int bm = blockIdx.y * TBM, bn = blockIdx.x * TBN;

    float c[2][4][4];
#pragma unroll
    for (int mi = 0; mi < 2; mi++)
#pragma unroll
        for (int ni = 0; ni < 4; ni++)
#pragma unroll
            for (int e = 0; e < 4; e++) c[mi][ni][e] = 0.f;

    for (int kk = 0; kk < K; kk += TBK) {
        // load A tile 64x16
#pragma unroll
        for (int it = 0; it < 8; it++) {
            int idx = it * 128 + tid;
            int r = idx >> 4, cc = idx & 15;
            float v = 0.f;
            if (bm + r < M && kk + cc < K) v = A[(long)(bm + r) * lda + kk + cc];
            As[r][cc] = to_tf32(v);
        }
        // load B tile 16x64 into Bs[k][n]
#pragma unroll
        for (int it = 0; it < 8; it++) {
            int idx = it * 128 + tid;
            float v = 0.f;
            if (NT) {
                int nc = idx >> 4, kr = idx & 15;
                if (bn + nc < N && kk + kr < K) v = B[(long)(bn + nc) * ldb + kk + kr];
                Bs[kr][nc] = to_tf32(v);
            } else {
                int kr = idx >> 6, nc = idx & 63;
                if (kk + kr < K && bn + nc < N) v = B[(long)(kk + kr) * ldb + bn + nc];
                Bs[kr][nc] = to_tf32(v);
            }
        }
        __syncthreads();

#pragma unroll
        for (int k8 = 0; k8 < TBK; k8 += 8) {
            uint32_t a[2][4], b[4][2];
#pragma unroll
            for (int mi = 0; mi < 2; mi++) {
                int m = m0w + mi * 16 + g;
                a[mi][0] = __float_as_uint(As[m    ][k8 + tig    ]);
                a[mi][1] = __float_as_uint(As[m + 8][k8 + tig    ]);
                a[mi][2] = __float_as_uint(As[m    ][k8 + tig + 4]);
                a[mi][3] = __float_as_uint(As[m + 8][k8 + tig + 4]);
            }
#pragma unroll
            for (int ni = 0; ni < 4; ni++) {
                int n = n0w + ni * 8 + g;
                b[ni][0] = __float_as_uint(Bs[k8 + tig    ][n]);
                b[ni][1] = __float_as_uint(Bs[k8 + tig + 4][n]);
            }
#pragma unroll
            for (int mi = 0; mi < 2; mi++)
#pragma unroll
                for (int ni = 0; ni < 4; ni++)
                    mma_tf32(c[mi][ni][0], c[mi][ni][1], c[mi][ni][2], c[mi][ni][3],
                             a[mi][0], a[mi][1], a[mi][2], a[mi][3],
                             b[ni][0], b[ni][1]);
        }
        __syncthreads();
    }

    // epilogue
#pragma unroll
    for (int mi = 0; mi < 2; mi++) {
#pragma unroll
        for (int ni = 0; ni < 4; ni++) {
#pragma unroll
            for (int e = 0; e < 4; e++) {
                int row = bm + m0w + mi * 16 + g + ((e >= 2) ? 8 : 0);
                int col = bn + n0w + ni * 8 + tig * 2 + (e & 1);
                if (row >= M || col >= N) continue;
                float v = c[mi][ni][e];
                if (bias) v += bias[col];
                v *= scale;
                if (act == 1) v = 0.5f * v * (1.f + erff(v * 0.70710678118654752f));
                long ci = (long)row * ldc + col;
                if (R) v += R[ci];
                C[ci] = v;
            }
        }
    }
}

// ---------------- elementwise / row kernels ----------------
__global__ __launch_bounds__(256) void embed_kernel(
    const int* __restrict__ tokens, const float* __restrict__ tok_emb,
    const float* __restrict__ pos_emb, float* __restrict__ x)
{
    int row = blockIdx.x;
    int t = row % TT;
    int tok = tokens[row];
    const float* te = tok_emb + (long)tok * DD;
    const float* pe = pos_emb + (long)t * DD;
    float* xr = x + (long)row * DD;
#pragma unroll
    for (int it = 0; it < 3; it++) {
        int j = threadIdx.x + it * 256;
        xr[j] = te[j] + pe[j];
    }
}

__global__ __launch_bounds__(256) void ln_kernel(
    const float* __restrict__ x, float* __restrict__ y,
    const float* __restrict__ g, const float* __restrict__ b)
{
    __shared__ float red[256];
    int row = blockIdx.x;
    const float* xr = x + (long)row * DD;
    float* yr = y + (long)row * DD;
    int tid = threadIdx.x;
    float v0 = xr[tid], v1 = xr[tid + 256], v2 = xr[tid + 512];
    float s = v0 + v1 + v2;
    red[tid] = s; __syncthreads();
    for (int st = 128; st > 0; st >>= 1) { if (tid < st) red[tid] += red[tid + st]; __syncthreads(); }
    float mean = red[0] * (1.f / DD);
    __syncthreads();
    float d0 = v0 - mean, d1 = v1 - mean, d2 = v2 - mean;
    red[tid] = d0 * d0 + d1 * d1 + d2 * d2; __syncthreads();
    for (int st = 128; st > 0; st >>= 1) { if (tid < st) red[tid] += red[tid + st]; __syncthreads(); }
    float inv = rsqrtf(red[0] * (1.f / DD) + 1e-5f);
    yr[tid]       = d0 * inv * g[tid]       + b[tid];
    yr[tid + 256] = d1 * inv * g[tid + 256] + b[tid + 256];
    yr[tid + 512] = d2 * inv * g[tid + 512] + b[tid + 512];
}

__global__ __launch_bounds__(256) void softmax_causal_kernel(float* __restrict__ S)
{
    __shared__ float red[256];
    int row = blockIdx.x;
    int i = row & (TT - 1);
    float* p = S + (long)row * TT;
    int tid = threadIdx.x;
    float v = (tid <= i) ? p[tid] : -1e30f;
    red[tid] = v; __syncthreads();
    for (int st = 128; st > 0; st >>= 1) { if (tid < st) red[tid] = fmaxf(red[tid], red[tid + st]); __syncthreads(); }
    float m = red[0]; __syncthreads();
    float e = (tid <= i) ? expf(v - m) : 0.f;
    red[tid] = e; __syncthreads();
    for (int st = 128; st > 0; st >>= 1) { if (tid < st) red[tid] += red[tid + st]; __syncthreads(); }
    p[tid] = e / red[0];
}

__global__ __launch_bounds__(256) void softmax_plain_kernel(float* __restrict__ S, int len)
{
    __shared__ float red[256];
    int row = blockIdx.x;
    float* p = S + (long)row * len;
    int tid = threadIdx.x;
    float vals[6];
    float m = -1e30f;
#pragma unroll
    for (int it = 0; it < 6; it++) {
        int j = tid + it * 256;
        float v = (j < len) ? p[j] : -1e30f;
        vals[it] = v;
        m = fmaxf(m, v);
    }
    red[tid] = m; __syncthreads();
    for (int st = 128; st > 0; st >>= 1) { if (tid < st) red[tid] = fmaxf(red[tid], red[tid + st]); __syncthreads(); }
    m = red[0]; __syncthreads();
    float s = 0.f;
#pragma unroll
    for (int it = 0; it < 6; it++) {
        int j = tid + it * 256;
        float e = (j < len) ? expf(vals[it] - m) : 0.f;
        vals[it] = e;
        s += e;
    }
    red[tid] = s; __syncthreads();
    for (int st = 128; st > 0; st >>= 1) { if (tid < st) red[tid] += red[tid + st]; __syncthreads(); }
    float inv = 1.f / red[0];
#pragma unroll
    for (int it = 0; it < 6; it++) {
        int j = tid + it * 256;
        if (j < len) p[j] = vals[it] * inv;
    }
}

// ---------------- host-side launch helpers ----------------
static inline void launch_nn(int M, int N, int K,
                             const float* A, int lda, long sA0, long sA1,
                             const float* B, int ldb, long sB0, long sB1,
                             float* C, int ldc, long sC0, long sC1,
                             int batch, int Hd,
                             const float* bias, const float* res,
                             float scale, int act)
{
    dim3 grd((N + TBN - 1) / TBN, (M + TBM - 1) / TBM, batch);
    gemm_tf32_kernel<0><<<grd, 128>>>(M, N, K, A, lda, sA0, sA1, B, ldb, sB0, sB1,
                                      C, ldc, sC0, sC1, Hd, bias, res, scale, act);
}

static inline void launch_nt(int M, int N, int K,
                             const float* A, int lda, long sA0, long sA1,
                             const float* B, int ldb, long sB0, long sB1,
                             float* C, int ldc, long sC0, long sC1,
                             int batch, int Hd, float scale)
{
    dim3 grd((N + TBN - 1) / TBN, (M + TBM - 1) / TBM, batch);
    gemm_tf32_kernel<1><<<grd, 128>>>(M, N, K, A, lda, sA0, sA1, B, ldb, sB0, sB1,
                                      C, ldc, sC0, sC1, Hd, nullptr, nullptr, scale, 0);
}

extern "C" void kernel_launch(void* const* d_in, const int* in_sizes, int n_in,
                              void* d_out, int out_size)
{
    (void)in_sizes; (void)n_in; (void)out_size;

    const int*   tokens  = (const int*)  d_in[0];
    const float* xa      = (const float*)d_in[1];
    const float* tok_emb = (const float*)d_in[2];
    const float* pos_emb = (const float*)d_in[3];
    const float* Wq      = (const float*)d_in[4];
    const float* bq      = (const float*)d_in[5];
    const float* Wk      = (const float*)d_in[6];
    const float* Wv      = (const float*)d_in[7];
    const float* bv      = (const float*)d_in[8];
    const float* Wo      = (const float*)d_in[9];
    const float* bo      = (const float*)d_in[10];
    const float* ln1_g   = (const float*)d_in[11];
    const float* ln1_b   = (const float*)d_in[12];
    const float* Wcq     = (const float*)d_in[13];
    const float* bcq     = (const float*)d_in[14];
    const float* Wck     = (const float*)d_in[15];
    const float* Wcv     = (const float*)d_in[16];
    const float* bcv     = (const float*)d_in[17];
    const float* Wco     = (const float*)d_in[18];
    const float* bco     = (const float*)d_in[19];
    const float* ln2_g   = (const float*)d_in[20];
    const float* ln2_b   = (const float*)d_in[21];
    const float* W1      = (const float*)d_in[22];
    const float* b1      = (const float*)d_in[23];
    const float* W2      = (const float*)d_in[24];
    const float* b2      = (const float*)d_in[25];
    const float* ln3_g   = (const float*)d_in[26];
    const float* ln3_b   = (const float*)d_in[27];
    const float* lnf_g   = (const float*)d_in[28];
    const float* lnf_b   = (const float*)d_in[29];

    float* out = (float*)d_out;
    float* out_logits = out;                                        // [B,T,V]
    float* out_chw    = out_logits + (size_t)BB * TT * VV;          // [(L/2)*H,T,TA]
    float* out_kv     = out_chw + (size_t)(LL / 2) * HH * TT * TAA; // [2L,B,T,D]

    float *x, *h, *q, *o, *sc, *ck, *cv, *hid;
    cudaGetSymbolAddress((void**)&x,   g_x);
    cudaGetSymbolAddress((void**)&h,   g_h);
    cudaGetSymbolAddress((void**)&q,   g_q);
    cudaGetSymbolAddress((void**)&o,   g_o);
    cudaGetSymbolAddress((void**)&sc,  g_sc);
    cudaGetSymbolAddress((void**)&ck,  g_ck);
    cudaGetSymbolAddress((void**)&cv,  g_cv);
    cudaGetSymbolAddress((void**)&hid, g_hid);

    embed_kernel<<<BT, 256>>>(tokens, tok_emb, pos_emb, x);

    const long DTD = (long)TT * DD;        // per-b stride in [B,T,D]
    const long TAD = (long)TAA * DD;       // per-b stride in [B,TA,D]

    for (int l = 0; l < LL; l++) {
        const float* Wq_l = Wq + (size_t)l * DD * DD;
        const float* Wk_l = Wk + (size_t)l * DD * DD;
        const float* Wv_l = Wv + (size_t)l * DD * DD;
        const float* Wo_l = Wo + (size_t)l * DD * DD;
        const float* Wcq_l = Wcq + (size_t)l * DD * DD;
        const float* Wck_l = Wck + (size_t)l * DD * DD;
        const float* Wcv_l = Wcv + (size_t)l * DD * DD;
        const float* Wco_l = Wco + (size_t)l * DD * DD;
        const float* W1_l = W1 + (size_t)l * DD * 4 * DD;
        const float* W2_l = W2 + (size_t)l * 4 * DD * DD;

        float* kout = out_kv + (size_t)(2 * l) * BT * DD;      // [B,T,D]
        float* vout = out_kv + (size_t)(2 * l + 1) * BT * DD;

        // ---- self attention ----
        ln_kernel<<<BT, 256>>>(x, h, ln1_g + l * DD, ln1_b + l * DD);
        launch_nn(BT, DD, DD, h, DD, 0, 0, Wq_l, DD, 0, 0, q, DD, 0, 0, 1, 1,
                  bq + l * DD, nullptr, SCALE_Q, 0);
        launch_nn(BT, DD, DD, h, DD, 0, 0, Wk_l, DD, 0, 0, kout, DD, 0, 0, 1, 1,
                  nullptr, nullptr, 1.f, 0);
        launch_nn(BT, DD, DD, h, DD, 0, 0, Wv_l, DD, 0, 0, vout, DD, 0, 0, 1, 1,
                  bv + l * DD, nullptr, 1.f, 0);
        launch_nt(TT, TT, DHH,
                  q,    DD, DTD, DHH,
                  kout, DD, DTD, DHH,
                  sc,   TT, (long)HH * TT * TT, (long)TT * TT,
                  BB * HH, HH, 1.f);
        softmax_causal_kernel<<<BB * HH * TT, 256>>>(sc);
        launch_nn(TT, DHH, TT,
                  sc,   TT, (long)HH * TT * TT, (long)TT * TT,
                  vout, DD, DTD, DHH,
                  o,    DD, DTD, DHH,
                  BB * HH, HH, nullptr, nullptr, 1.f, 0);
        launch_nn(BT, DD, DD, o, DD, 0, 0, Wo_l, DD, 0, 0, x, DD, 0, 0, 1, 1,
                  bo + l * DD, x, 1.f, 0);

        // ---- cross attention ----
        ln_kernel<<<BT, 256>>>(x, h, ln2_g + l * DD, ln2_b + l * DD);
        launch_nn(BT, DD, DD, h, DD, 0, 0, Wcq_l, DD, 0, 0, q, DD, 0, 0, 1, 1,
                  bcq + l * DD, nullptr, SCALE_Q, 0);
        launch_nn(BB * TAA, DD, DD, xa, DD, 0, 0, Wck_l, DD, 0, 0, ck, DD, 0, 0, 1, 1,
                  nullptr, nullptr, 1.f, 0);
        launch_nn(BB * TAA, DD, DD, xa, DD, 0, 0, Wcv_l, DD, 0, 0, cv, DD, 0, 0, 1, 1,
                  bcv + l * DD, nullptr, 1.f, 0);
        launch_nt(TT, TAA, DHH,
                  q,  DD, DTD, DHH,
                  ck, DD, TAD, DHH,
                  sc, TAA, (long)HH * TT * TAA, (long)TT * TAA,
                  BB * HH, HH, 1.f);
        if (l >= LL / 2) {
            cudaMemcpyAsync(out_chw + (size_t)(l - LL / 2) * HH * TT * TAA, sc,
                            sizeof(float) * (size_t)HH * TT * TAA,
                            cudaMemcpyDeviceToDevice);
        }
        softmax_plain_kernel<<<BB * HH * TT, 256>>>(sc, TAA);
        launch_nn(TT, DHH, TAA,
                  sc, TAA, (long)HH * TT * TAA, (long)TT * TAA,
                  cv, DD, TAD, DHH,
                  o,  DD, DTD, DHH,
                  BB * HH, HH, nullptr, nullptr, 1.f, 0);
        launch_nn(BT, DD, DD, o, DD, 0, 0, Wco_l, DD, 0, 0, x, DD, 0, 0, 1, 1,
                  bco + l * DD, x, 1.f, 0);

        // ---- MLP ----
        ln_kernel<<<BT, 256>>>(x, h, ln3_g + l * DD, ln3_b + l * DD);
        launch_nn(BT, 4 * DD, DD, h, DD, 0, 0, W1_l, 4 * DD, 0, 0, hid, 4 * DD, 0, 0,
                  1, 1, b1 + (size_t)l * 4 * DD, nullptr, 1.f, 1);
        launch_nn(BT, DD, 4 * DD, hid, 4 * DD, 0, 0, W2_l, DD, 0, 0, x, DD, 0, 0,
                  1, 1, b2 + l * DD, x, 1.f, 0);
    }

    // final LN + tied-embedding logits
    ln_kernel<<<BT, 256>>>(x, h, lnf_g, lnf_b);
    launch_nt(BT, VV, DD,
              h, DD, 0, 0,
              tok_emb, DD, 0, 0,
              out_logits, VV, 0, 0,
              1, 1, 1.f);
}